// round 10
// baseline (speedup 1.0000x reference)
#include <cuda_runtime.h>

#define BB 8
#define TT 16
#define HH 96
#define WW 96
#define CI 8
#define FF 64

#define NPIX (BB*HH*WW*FF)   // 4,718,592 floats per state buffer

#define SH_STRIDE 68         // 68 mod 32 == 4 -> conflict-free LDS.128 phases
#define SX_STRIDE 12         // 12 mod 32 -> conflict-free for 8-lane phases

__device__ float g_h0[NPIX];
__device__ float g_h1[NPIX];
__device__ float g_c[NPIX];

__device__ __forceinline__ float hsig(float z) {
    return fminf(fmaxf(fmaf(z, 0.2f, 0.5f), 0.0f), 1.0f);
}

__global__ void zero_kernel(float* a, float* b, int n4) {
    int i = blockIdx.x * blockDim.x + threadIdx.x;
    float4 z = make_float4(0.f, 0.f, 0.f, 0.f);
    if (i < n4) {
        ((float4*)a)[i] = z;
        ((float4*)b)[i] = z;
    }
}

// One ConvLSTM step. Block = 8x8 pixel tile, 256 threads.
// Thread (pg, cg): pg = tid&15 -> 4 pixels {pg, pg+16, pg+32, pg+48} of the 64-pixel
// tile (same column, rows py0+2u); cg = tid>>4 -> filters fb..fb+3 (fb = cg*4),
// across all 4 gates (channels q*64+fb+j). 64 accumulators/thread.
// Each weight float4 load feeds 16 FMAs (4 pixels x 4 channels) -> FMA-bound.
__global__ __launch_bounds__(256, 2)
void step_kernel(const float* __restrict__ x,
                 const float* __restrict__ Wx,
                 const float* __restrict__ Wh,
                 const float* __restrict__ bias,
                 const float* __restrict__ h_in,
                 float* __restrict__ c_st,
                 float* __restrict__ h_out,
                 int t)
{
    __shared__ float sh[10 * 10 * SH_STRIDE];   // h halo tile, padded (27.2 KB)
    __shared__ float sx[10 * 10 * SX_STRIDE];   // x halo tile, padded (4.8 KB)

    const int tid = threadIdx.x;
    const int pg  = tid & 15;       // pixel group 0..15
    const int cg  = tid >> 4;       // filter quad 0..15
    const int fb  = cg * 4;         // filter base
    const int py0 = pg >> 3;        // 0..1
    const int px  = pg & 7;         // 0..7
    const int bx0 = blockIdx.x * 8;
    const int by0 = blockIdx.y * 8;
    const int bb  = blockIdx.z;

    // ---- stage h halo: 10x10 pixels x 64 ch = 1600 float4 ----
    for (int i = tid; i < 1600; i += 256) {
        int ch4 = i & 15;
        int pix = i >> 4;
        int r  = pix / 10;
        int cc = pix - r * 10;
        int gy = by0 + r - 1;
        int gx = bx0 + cc - 1;
        float4 v = make_float4(0.f, 0.f, 0.f, 0.f);
        if ((unsigned)gy < 96u && (unsigned)gx < 96u)
            v = __ldg((const float4*)(h_in + ((bb * 96 + gy) * 96 + gx) * 64 + ch4 * 4));
        *(float4*)(sh + pix * SH_STRIDE + ch4 * 4) = v;
    }
    // ---- stage x halo: 10x10 pixels x 8 ch = 200 float4 ----
    for (int i = tid; i < 200; i += 256) {
        int ch4 = i & 1;
        int pix = i >> 1;
        int r  = pix / 10;
        int cc = pix - r * 10;
        int gy = by0 + r - 1;
        int gx = bx0 + cc - 1;
        float4 v = make_float4(0.f, 0.f, 0.f, 0.f);
        if ((unsigned)gy < 96u && (unsigned)gx < 96u)
            v = __ldg((const float4*)(x + (((bb * TT + t) * 96 + gy) * 96 + gx) * 8 + ch4 * 4));
        *(float4*)(sx + pix * SX_STRIDE + ch4 * 4) = v;
    }
    __syncthreads();

    // acc[q][u] = float4 over 4 filters j, for gate q, pixel slot u
    float4 acc[4][4];
    #pragma unroll
    for (int q = 0; q < 4; q++) {
        float4 bv = __ldg((const float4*)(bias + q * 64 + fb));
        #pragma unroll
        for (int u = 0; u < 4; u++) acc[q][u] = bv;
    }

    // ---- input conv: K = 9 * 8 ----
    #pragma unroll 1
    for (int k = 0; k < 9; k++) {
        const int ky = k / 3;
        const int kx = k - ky * 3;
        const float* ab0 = sx + ((py0 + 0 + ky) * 10 + (px + kx)) * SX_STRIDE;
        const float* ab1 = ab0 + 2 * 10 * SX_STRIDE;
        const float* ab2 = ab1 + 2 * 10 * SX_STRIDE;
        const float* ab3 = ab2 + 2 * 10 * SX_STRIDE;
        const float* wkb = Wx + k * 8 * 256 + fb;
        #pragma unroll
        for (int ic0 = 0; ic0 < 8; ic0 += 4) {
            float4 av[4];
            av[0] = *(const float4*)(ab0 + ic0);
            av[1] = *(const float4*)(ab1 + ic0);
            av[2] = *(const float4*)(ab2 + ic0);
            av[3] = *(const float4*)(ab3 + ic0);
            #pragma unroll
            for (int v = 0; v < 4; v++) {
                const float* w = wkb + (ic0 + v) * 256;
                float4 w0 = __ldg((const float4*)(w));
                float4 w1 = __ldg((const float4*)(w + 64));
                float4 w2 = __ldg((const float4*)(w + 128));
                float4 w3 = __ldg((const float4*)(w + 192));
                #pragma unroll
                for (int u = 0; u < 4; u++) {
                    const float a = (v == 0) ? av[u].x : (v == 1) ? av[u].y
                                  : (v == 2) ? av[u].z : av[u].w;
                    acc[0][u].x = fmaf(a, w0.x, acc[0][u].x);
                    acc[0][u].y = fmaf(a, w0.y, acc[0][u].y);
                    acc[0][u].z = fmaf(a, w0.z, acc[0][u].z);
                    acc[0][u].w = fmaf(a, w0.w, acc[0][u].w);
                    acc[1][u].x = fmaf(a, w1.x, acc[1][u].x);
                    acc[1][u].y = fmaf(a, w1.y, acc[1][u].y);
                    acc[1][u].z = fmaf(a, w1.z, acc[1][u].z);
                    acc[1][u].w = fmaf(a, w1.w, acc[1][u].w);
                    acc[2][u].x = fmaf(a, w2.x, acc[2][u].x);
                    acc[2][u].y = fmaf(a, w2.y, acc[2][u].y);
                    acc[2][u].z = fmaf(a, w2.z, acc[2][u].z);
                    acc[2][u].w = fmaf(a, w2.w, acc[2][u].w);
                    acc[3][u].x = fmaf(a, w3.x, acc[3][u].x);
                    acc[3][u].y = fmaf(a, w3.y, acc[3][u].y);
                    acc[3][u].z = fmaf(a, w3.z, acc[3][u].z);
                    acc[3][u].w = fmaf(a, w3.w, acc[3][u].w);
                }
            }
        }
    }

    // ---- recurrent conv: K = 9 * 64 (dominant work) ----
    #pragma unroll 1
    for (int k = 0; k < 9; k++) {
        const int ky = k / 3;
        const int kx = k - ky * 3;
        const float* ab0 = sh + ((py0 + 0 + ky) * 10 + (px + kx)) * SH_STRIDE;
        const float* ab1 = ab0 + 2 * 10 * SH_STRIDE;
        const float* ab2 = ab1 + 2 * 10 * SH_STRIDE;
        const float* ab3 = ab2 + 2 * 10 * SH_STRIDE;
        const float* wkb = Wh + k * 64 * 256 + fb;
        #pragma unroll 2
        for (int ic0 = 0; ic0 < 64; ic0 += 4) {
            float4 av[4];
            av[0] = *(const float4*)(ab0 + ic0);
            av[1] = *(const float4*)(ab1 + ic0);
            av[2] = *(const float4*)(ab2 + ic0);
            av[3] = *(const float4*)(ab3 + ic0);
            #pragma unroll
            for (int v = 0; v < 4; v++) {
                const float* w = wkb + (ic0 + v) * 256;
                float4 w0 = __ldg((const float4*)(w));
                float4 w1 = __ldg((const float4*)(w + 64));
                float4 w2 = __ldg((const float4*)(w + 128));
                float4 w3 = __ldg((const float4*)(w + 192));
                #pragma unroll
                for (int u = 0; u < 4; u++) {
                    const float a = (v == 0) ? av[u].x : (v == 1) ? av[u].y
                                  : (v == 2) ? av[u].z : av[u].w;
                    acc[0][u].x = fmaf(a, w0.x, acc[0][u].x);
                    acc[0][u].y = fmaf(a, w0.y, acc[0][u].y);
                    acc[0][u].z = fmaf(a, w0.z, acc[0][u].z);
                    acc[0][u].w = fmaf(a, w0.w, acc[0][u].w);
                    acc[1][u].x = fmaf(a, w1.x, acc[1][u].x);
                    acc[1][u].y = fmaf(a, w1.y, acc[1][u].y);
                    acc[1][u].z = fmaf(a, w1.z, acc[1][u].z);
                    acc[1][u].w = fmaf(a, w1.w, acc[1][u].w);
                    acc[2][u].x = fmaf(a, w2.x, acc[2][u].x);
                    acc[2][u].y = fmaf(a, w2.y, acc[2][u].y);
                    acc[2][u].z = fmaf(a, w2.z, acc[2][u].z);
                    acc[2][u].w = fmaf(a, w2.w, acc[2][u].w);
                    acc[3][u].x = fmaf(a, w3.x, acc[3][u].x);
                    acc[3][u].y = fmaf(a, w3.y, acc[3][u].y);
                    acc[3][u].z = fmaf(a, w3.z, acc[3][u].z);
                    acc[3][u].w = fmaf(a, w3.w, acc[3][u].w);
                }
            }
        }
    }

    // ---- gate epilogue: i,f,g,o -> c_new, h_new (thread-local) ----
    #pragma unroll
    for (int u = 0; u < 4; u++) {
        const int gy = by0 + py0 + 2 * u;
        const int gx = bx0 + px;
        const int base = ((bb * 96 + gy) * 96 + gx) * 64 + fb;
        float4 cv = *(const float4*)(c_st + base);
        float cin[4] = {cv.x, cv.y, cv.z, cv.w};
        float iv[4] = {acc[0][u].x, acc[0][u].y, acc[0][u].z, acc[0][u].w};
        float fv[4] = {acc[1][u].x, acc[1][u].y, acc[1][u].z, acc[1][u].w};
        float gv[4] = {acc[2][u].x, acc[2][u].y, acc[2][u].z, acc[2][u].w};
        float ov[4] = {acc[3][u].x, acc[3][u].y, acc[3][u].z, acc[3][u].w};
        float cn[4], hn[4];
        #pragma unroll
        for (int j = 0; j < 4; j++) {
            float ig  = hsig(iv[j]);
            float fg_ = hsig(fv[j]);
            float gg  = tanhf(gv[j]);
            float og  = hsig(ov[j]);
            cn[j] = fg_ * cin[j] + ig * gg;
            hn[j] = og * tanhf(cn[j]);
        }
        *(float4*)(c_st + base)  = make_float4(cn[0], cn[1], cn[2], cn[3]);
        *(float4*)(h_out + base) = make_float4(hn[0], hn[1], hn[2], hn[3]);
    }
}

extern "C" void kernel_launch(void* const* d_in, const int* in_sizes, int n_in,
                              void* d_out, int out_size) {
    const float* x    = (const float*)d_in[0];
    const float* Wx   = (const float*)d_in[1];
    const float* Wh   = (const float*)d_in[2];
    const float* bias = (const float*)d_in[3];
    float* out = (float*)d_out;

    float *h0, *h1, *c;
    cudaGetSymbolAddress((void**)&h0, g_h0);
    cudaGetSymbolAddress((void**)&h1, g_h1);
    cudaGetSymbolAddress((void**)&c,  g_c);

    // zero h(0) and c(0) every call (graph replays must be deterministic)
    int n4 = NPIX / 4;
    zero_kernel<<<(n4 + 255) / 256, 256>>>(h0, c, n4);

    dim3 grid(12, 12, BB);   // 12x12 spatial tiles of 8x8, per batch
    for (int t = 0; t < TT; t++) {
        const float* hin = (t & 1) ? h1 : h0;
        float* hout = (t == TT - 1) ? out : ((t & 1) ? h0 : h1);
        step_kernel<<<grid, 256>>>(x, Wx, Wh, bias, hin, c, hout, t);
    }
}

// round 13
// speedup vs baseline: 1.7158x; 1.7158x over previous
#include <cuda_runtime.h>
#include <cuda_bf16.h>
#include <cstdint>

#define BB 8
#define TT 16
#define NPIX (8*96*96*64)
#define NPIXG 1179648            // B*T*H*W = 8*16*96*96
#define ZXN  301989888           // NPIXG * 256

// ---------------- persistent device state ----------------
__device__ __nv_bfloat16 g_hh0[NPIX], g_hh1[NPIX];   // h hi ping-pong
__device__ __nv_bfloat16 g_hl0[NPIX], g_hl1[NPIX];   // h lo
__device__ float         g_c[NPIX];
__device__ float         g_zx[ZXN];                  // x-conv + bias, n-permuted, fp32
__device__ __nv_bfloat16 g_whp_hi[9*256*64], g_whp_lo[9*256*64];  // [tap][n_new][k]
__device__ __nv_bfloat16 g_wxp_hi[256*80],  g_wxp_lo[256*80];     // [n_new][k pad 80]
__device__ float         g_biasp[256];

// ---------------- helpers ----------------
__device__ __forceinline__ uint32_t smem_u32(const void* p) {
    uint32_t a;
    asm("{ .reg .u64 t; cvta.to.shared.u64 t, %1; cvt.u32.u64 %0, t; }" : "=r"(a) : "l"(p));
    return a;
}
__device__ __forceinline__ float hsig(float z) {
    return fminf(fmaxf(fmaf(z, 0.2f, 0.5f), 0.0f), 1.0f);
}

#define LDSM4(r0,r1,r2,r3,addr) \
    asm volatile("ldmatrix.sync.aligned.m8n8.x4.shared.b16 {%0,%1,%2,%3}, [%4];" \
                 : "=r"(r0),"=r"(r1),"=r"(r2),"=r"(r3) : "r"(addr))

#define MMA(d,a0,a1,a2,a3,b0,b1) \
    asm volatile("mma.sync.aligned.m16n8k16.row.col.f32.bf16.bf16.f32 " \
                 "{%0,%1,%2,%3},{%4,%5,%6,%7},{%8,%9},{%0,%1,%2,%3};" \
                 : "+f"((d)[0]),"+f"((d)[1]),"+f"((d)[2]),"+f"((d)[3]) \
                 : "r"(a0),"r"(a1),"r"(a2),"r"(a3),"r"(b0),"r"(b1))

#define CPA16(dst,src) \
    asm volatile("cp.async.cg.shared.global [%0], [%1], 16;" :: "r"(dst), "l"(src) : "memory")
#define CPA_COMMIT() asm volatile("cp.async.commit_group;" ::: "memory")
#define CPA_WAIT1()  asm volatile("cp.async.wait_group 1;" ::: "memory")
#define CPA_WAIT0()  asm volatile("cp.async.wait_group 0;" ::: "memory")

// ---------------- prep kernels ----------------
__global__ void prep_wh(const float* __restrict__ Wh) {
    int i = blockIdx.x * blockDim.x + threadIdx.x;
    if (i < 9*256*64) {
        int tap = i >> 14, rem = i & 16383, n = rem >> 6, k = rem & 63;
        int f = n >> 2, g = n & 3, no = g * 64 + f;
        float v = Wh[(tap * 64 + k) * 256 + no];
        __nv_bfloat16 hi = __float2bfloat16_rn(v);
        g_whp_hi[i] = hi;
        g_whp_lo[i] = __float2bfloat16_rn(v - __bfloat162float(hi));
    }
}
__global__ void prep_wx(const float* __restrict__ Wx, const float* __restrict__ b) {
    int i = blockIdx.x * blockDim.x + threadIdx.x;
    if (i < 256*80) {
        int n = i / 80, k = i - n * 80;
        int f = n >> 2, g = n & 3, no = g * 64 + f;
        float v = (k < 72) ? Wx[k * 256 + no] : 0.f;
        __nv_bfloat16 hi = __float2bfloat16_rn(v);
        g_wxp_hi[i] = hi;
        g_wxp_lo[i] = __float2bfloat16_rn(v - __bfloat162float(hi));
        if (k == 0) g_biasp[n] = b[no];
    }
}
__global__ void zero_state() {
    int i = blockIdx.x * blockDim.x + threadIdx.x;
    if (i < NPIX/8) {
        float4 z4 = make_float4(0.f,0.f,0.f,0.f);
        ((float4*)g_c)[2*i]   = z4;
        ((float4*)g_c)[2*i+1] = z4;
        uint4 z = make_uint4(0,0,0,0);
        ((uint4*)g_hh0)[i] = z;
        ((uint4*)g_hl0)[i] = z;
    }
}

// ---------------- x-conv precompute: z_x = conv(x,Wx)+bias, all (b,t) ----------------
#define PXF 0
#define PXA_HI 5760
#define PXA_LO 28288
#define PB_HI 50816
#define PB_LO 95872
#define SMEM_PRE 140928

__global__ __launch_bounds__(512,1)
void xconv_mma(const float* __restrict__ x, float* __restrict__ zx)
{
    extern __shared__ char smem[];
    const uint32_t sbb = smem_u32(smem);
    const int tid = threadIdx.x, lane = tid & 31, wid = tid >> 5;
    const int bx0 = blockIdx.x * 8, by0 = blockIdx.y * 16, bt = blockIdx.z;
    const int m0 = (wid >> 2) * 32, n0 = (wid & 3) * 64;

    // fp32 x halo: 18x10 px, 8 ch
    for (int i = tid; i < 1440; i += 512) {
        int pix = i >> 3, ch = i & 7;
        int r = pix / 10, c = pix - r * 10;
        int gy = by0 + r - 1, gx = bx0 + c - 1;
        float v = 0.f;
        if ((unsigned)gy < 96u && (unsigned)gx < 96u)
            v = x[((bt * 96 + gy) * 96 + gx) * 8 + ch];
        *(float*)(smem + PXF + (pix * 8 + ch) * 4) = v;
    }
    __syncthreads();

    // build im2col A (128 px x 80 k), split hi/lo, stride 176B
    for (int i = tid; i < 128 * 80; i += 512) {
        int p = i / 80, k = i - p * 80;
        float v = 0.f;
        if (k < 72) {
            int tap = k >> 3, ci = k & 7;
            int ky = tap / 3, kx = tap - ky * 3;
            int py = p >> 3, px = p & 7;
            v = *(float*)(smem + PXF + (((py + ky) * 10 + px + kx) * 8 + ci) * 4);
        }
        __nv_bfloat16 hi = __float2bfloat16_rn(v);
        *(__nv_bfloat16*)(smem + PXA_HI + p * 176 + k * 2) = hi;
        *(__nv_bfloat16*)(smem + PXA_LO + p * 176 + k * 2) =
            __float2bfloat16_rn(v - __bfloat162float(hi));
    }
    // B: [256][80] hi/lo -> stride 176B
    for (int i = tid; i < 2560; i += 512) {
        int row = i / 10, ch = i - row * 10;
        *(uint4*)(smem + PB_HI + row * 176 + ch * 16) =
            *(const uint4*)((const char*)g_wxp_hi + row * 160 + ch * 16);
        *(uint4*)(smem + PB_LO + row * 176 + ch * 16) =
            *(const uint4*)((const char*)g_wxp_lo + row * 160 + ch * 16);
    }
    __syncthreads();

    const int grp = lane >> 3, lr = lane & 7;
    const int koff = (grp >> 1) * 8;
    const int am0 = m0 + lr + (grp & 1) * 8;
    const int am1 = am0 + 16;
    const uint32_t aP0 = sbb + PXA_HI + am0 * 176 + koff * 2;
    const uint32_t aP1 = sbb + PXA_HI + am1 * 176 + koff * 2;
    uint32_t bRel[4];
    #pragma unroll
    for (int ng = 0; ng < 4; ng++)
        bRel[ng] = (uint32_t)(n0 + ng * 16 + (grp & 1) * 8 + lr) * 176 + koff * 2;
    const uint32_t bB = sbb + PB_HI;

    float acc[2][8][4];
    #pragma unroll
    for (int mf = 0; mf < 2; mf++)
        #pragma unroll
        for (int nf = 0; nf < 8; nf++)
            #pragma unroll
            for (int q = 0; q < 4; q++) acc[mf][nf][q] = 0.f;

    #pragma unroll
    for (int ks = 0; ks < 5; ks++) {
        const uint32_t o = ks * 32;
        uint32_t ah[2][4], al[2][4], bm[4][4];
        LDSM4(ah[0][0],ah[0][1],ah[0][2],ah[0][3], aP0 + o);
        LDSM4(ah[1][0],ah[1][1],ah[1][2],ah[1][3], aP1 + o);
        LDSM4(al[0][0],al[0][1],al[0][2],al[0][3], aP0 + (PXA_LO-PXA_HI) + o);
        LDSM4(al[1][0],al[1][1],al[1][2],al[1][3], aP1 + (PXA_LO-PXA_HI) + o);
        #pragma unroll
        for (int ng = 0; ng < 4; ng++)
            LDSM4(bm[ng][0],bm[ng][1],bm[ng][2],bm[ng][3], bB + bRel[ng] + o);
        #pragma unroll
        for (int mf = 0; mf < 2; mf++)
            #pragma unroll
            for (int nf = 0; nf < 8; nf++) {
                int ng = nf >> 1, s = nf & 1;
                MMA(acc[mf][nf], ah[mf][0],ah[mf][1],ah[mf][2],ah[mf][3], bm[ng][s], bm[ng][s+2]);
                MMA(acc[mf][nf], al[mf][0],al[mf][1],al[mf][2],al[mf][3], bm[ng][s], bm[ng][s+2]);
            }
        #pragma unroll
        for (int ng = 0; ng < 4; ng++)
            LDSM4(bm[ng][0],bm[ng][1],bm[ng][2],bm[ng][3], bB + (PB_LO-PB_HI) + bRel[ng] + o);
        #pragma unroll
        for (int mf = 0; mf < 2; mf++)
            #pragma unroll
            for (int nf = 0; nf < 8; nf++) {
                int ng = nf >> 1, s = nf & 1;
                MMA(acc[mf][nf], ah[mf][0],ah[mf][1],ah[mf][2],ah[mf][3], bm[ng][s], bm[ng][s+2]);
            }
    }

    // store z_x (+bias), n_new-major
    #pragma unroll
    for (int mf = 0; mf < 2; mf++)
        #pragma unroll
        for (int nf = 0; nf < 8; nf++) {
            int coln = n0 + 8 * nf + 2 * (lane & 3);
            float b0 = __ldg(g_biasp + coln), b1 = __ldg(g_biasp + coln + 1);
            int ma = m0 + 16 * mf + (lane >> 2);
            int gya = by0 + (ma >> 3), gxa = bx0 + (ma & 7);
            int zA = ((bt * 96 + gya) * 96 + gxa) * 256 + coln;
            *(float2*)(zx + zA) = make_float2(acc[mf][nf][0] + b0, acc[mf][nf][1] + b1);
            int mb = ma + 8;
            int gyb = by0 + (mb >> 3), gxb = bx0 + (mb & 7);
            int zB = ((bt * 96 + gyb) * 96 + gxb) * 256 + coln;
            *(float2*)(zx + zB) = make_float2(acc[mf][nf][2] + b0, acc[mf][nf][3] + b1);
        }
}

// ---------------- recurrent step ----------------
#define SHH 0
#define SHL 25920
#define SBO 51840
#define SB_STAGE 73728
#define SB_LOO 36864
#define SMEM_STEP 199296

__device__ __forceinline__ void issueB(uint32_t sbb, int stage, int tap, int tid) {
    uint32_t dh = sbb + SBO + stage * SB_STAGE;
    const char* sh_ = (const char*)g_whp_hi + tap * 32768;
    const char* sl_ = (const char*)g_whp_lo + tap * 32768;
    #pragma unroll
    for (int j = 0; j < 4; j++) {
        int i = tid + j * 512;
        int row = i >> 3, ch = i & 7;
        CPA16(dh + row * 144 + ch * 16,           sh_ + row * 128 + ch * 16);
        CPA16(dh + SB_LOO + row * 144 + ch * 16,  sl_ + row * 128 + ch * 16);
    }
    CPA_COMMIT();
}

__global__ __launch_bounds__(512,1)
void step_mma(const __nv_bfloat16* __restrict__ hh_in, const __nv_bfloat16* __restrict__ hl_in,
              __nv_bfloat16* __restrict__ hh_out, __nv_bfloat16* __restrict__ hl_out,
              float* __restrict__ c_st, const float* __restrict__ zx,
              float* __restrict__ out, int t, int wout)
{
    extern __shared__ char smem[];
    const uint32_t sbb = smem_u32(smem);
    const int tid = threadIdx.x, lane = tid & 31, wid = tid >> 5;
    const int bx0 = blockIdx.x * 8, by0 = blockIdx.y * 16, bb = blockIdx.z;
    const int m0 = (wid >> 2) * 32, n0 = (wid & 3) * 64;

    // h halo hi/lo: 18x10 px x 64 bf16, stride 144B
    for (int i = tid; i < 1440; i += 512) {
        int pix = i >> 3, ch = i & 7;
        int r = pix / 10, c = pix - r * 10;
        int gy = by0 + r - 1, gx = bx0 + c - 1;
        uint4 vh = make_uint4(0,0,0,0), vl = vh;
        if ((unsigned)gy < 96u && (unsigned)gx < 96u) {
            int b = ((bb * 96 + gy) * 96 + gx) * 64 + ch * 8;
            vh = *(const uint4*)(hh_in + b);
            vl = *(const uint4*)(hl_in + b);
        }
        *(uint4*)(smem + SHH + pix * 144 + ch * 16) = vh;
        *(uint4*)(smem + SHL + pix * 144 + ch * 16) = vl;
    }

    // prologue: B(0)->s0, B(1)->s1
    issueB(sbb, 0, 0, tid);
    issueB(sbb, 1, 1, tid);

    const int grp = lane >> 3, lr = lane & 7;
    const int koff = (grp >> 1) * 8;
    const int am0 = m0 + lr + (grp & 1) * 8;
    const int am1 = am0 + 16;
    const int pya0 = am0 >> 3, pxa0 = am0 & 7;
    const int pya1 = am1 >> 3, pxa1 = am1 & 7;
    uint32_t bRel[4];
    #pragma unroll
    for (int ng = 0; ng < 4; ng++)
        bRel[ng] = (uint32_t)(n0 + ng * 16 + (grp & 1) * 8 + lr) * 144 + koff * 2;

    float acc[2][8][4];
    #pragma unroll
    for (int mf = 0; mf < 2; mf++)
        #pragma unroll
        for (int nf = 0; nf < 8; nf++)
            #pragma unroll
            for (int q = 0; q < 4; q++) acc[mf][nf][q] = 0.f;

    __syncthreads();   // halo visible

    #pragma unroll 1
    for (int tap = 0; tap < 9; tap++) {
        if (tap < 7) { CPA_WAIT1(); } else { CPA_WAIT0(); }
        __syncthreads();
        const int ky = tap / 3, kx = tap - ky * 3;
        const uint32_t aH0 = sbb + SHH + (((pya0 + ky) * 10 + pxa0 + kx) * 144 + koff * 2);
        const uint32_t aH1 = sbb + SHH + (((pya1 + ky) * 10 + pxa1 + kx) * 144 + koff * 2);
        const uint32_t bB = sbb + SBO + (tap & 1) * SB_STAGE;

        #pragma unroll
        for (int ks = 0; ks < 4; ks++) {
            const uint32_t o = ks * 32;
            uint32_t ah[2][4], al[2][4], bm[4][4];
            LDSM4(ah[0][0],ah[0][1],ah[0][2],ah[0][3], aH0 + o);
            LDSM4(ah[1][0],ah[1][1],ah[1][2],ah[1][3], aH1 + o);
            LDSM4(al[0][0],al[0][1],al[0][2],al[0][3], aH0 + (SHL-SHH) + o);
            LDSM4(al[1][0],al[1][1],al[1][2],al[1][3], aH1 + (SHL-SHH) + o);
            #pragma unroll
            for (int ng = 0; ng < 4; ng++)
                LDSM4(bm[ng][0],bm[ng][1],bm[ng][2],bm[ng][3], bB + bRel[ng] + o);
            #pragma unroll
            for (int mf = 0; mf < 2; mf++)
                #pragma unroll
                for (int nf = 0; nf < 8; nf++) {
                    int ng = nf >> 1, s = nf & 1;
                    MMA(acc[mf][nf], ah[mf][0],ah[mf][1],ah[mf][2],ah[mf][3], bm[ng][s], bm[ng][s+2]);
                    MMA(acc[mf][nf], al[mf][0],al[mf][1],al[mf][2],al[mf][3], bm[ng][s], bm[ng][s+2]);
                }
            #pragma unroll
            for (int ng = 0; ng < 4; ng++)
                LDSM4(bm[ng][0],bm[ng][1],bm[ng][2],bm[ng][3], bB + SB_LOO + bRel[ng] + o);
            #pragma unroll
            for (int mf = 0; mf < 2; mf++)
                #pragma unroll
                for (int nf = 0; nf < 8; nf++) {
                    int ng = nf >> 1, s = nf & 1;
                    MMA(acc[mf][nf], ah[mf][0],ah[mf][1],ah[mf][2],ah[mf][3], bm[ng][s], bm[ng][s+2]);
                }
        }
        __syncthreads();
        if (tap + 2 < 9) issueB(sbb, tap & 1, tap + 2, tid);
    }

    // ---- epilogue: butterfly gate exchange + LSTM update ----
    const int odd = lane & 1;
    #pragma unroll
    for (int mf = 0; mf < 2; mf++)
        #pragma unroll
        for (int nf = 0; nf < 8; nf++) {
            float c0 = acc[mf][nf][0], c1 = acc[mf][nf][1];
            float c2 = acc[mf][nf][2], c3 = acc[mf][nf][3];
            float e0 = __shfl_xor_sync(0xFFFFFFFFu, c0, 1);
            float e1 = __shfl_xor_sync(0xFFFFFFFFu, c1, 1);
            float e2 = __shfl_xor_sync(0xFFFFFFFFu, c2, 1);
            float e3 = __shfl_xor_sync(0xFFFFFFFFu, c3, 1);
            float zi = odd ? e2 : c0;
            float zf = odd ? e3 : c1;
            float zg = odd ? c2 : e0;
            float zo = odd ? c3 : e1;
            int m = m0 + 16 * mf + (lane >> 2) + (odd ? 8 : 0);
            int f = ((n0 + 8 * nf) >> 2) + ((lane & 3) >> 1);
            int gy = by0 + (m >> 3), gx = bx0 + (m & 7);
            int pixb = ((bb * 96 + gy) * 96 + gx) * 64 + f;
            int zxi = (((bb * 16 + t) * 96 + gy) * 96 + gx) * 256 + f * 4;
            float4 z4 = *(const float4*)(zx + zxi);
            zi += z4.x; zf += z4.y; zg += z4.z; zo += z4.w;
            float cin = c_st[pixb];
            float cn = hsig(zf) * cin + hsig(zi) * tanhf(zg);
            float hn = hsig(zo) * tanhf(cn);
            c_st[pixb] = cn;
            __nv_bfloat16 hhi = __float2bfloat16_rn(hn);
            hh_out[pixb] = hhi;
            hl_out[pixb] = __float2bfloat16_rn(hn - __bfloat162float(hhi));
            if (wout) out[pixb] = hn;
        }
}

// ---------------- launcher ----------------
extern "C" void kernel_launch(void* const* d_in, const int* in_sizes, int n_in,
                              void* d_out, int out_size) {
    const float* x    = (const float*)d_in[0];
    const float* Wx   = (const float*)d_in[1];
    const float* Wh   = (const float*)d_in[2];
    const float* bias = (const float*)d_in[3];
    float* out = (float*)d_out;

    cudaFuncSetAttribute(xconv_mma, cudaFuncAttributeMaxDynamicSharedMemorySize, SMEM_PRE);
    cudaFuncSetAttribute(step_mma,  cudaFuncAttributeMaxDynamicSharedMemorySize, SMEM_STEP);

    __nv_bfloat16 *hh0, *hh1, *hl0, *hl1;
    float *c, *zx;
    cudaGetSymbolAddress((void**)&hh0, g_hh0);
    cudaGetSymbolAddress((void**)&hh1, g_hh1);
    cudaGetSymbolAddress((void**)&hl0, g_hl0);
    cudaGetSymbolAddress((void**)&hl1, g_hl1);
    cudaGetSymbolAddress((void**)&c,  g_c);
    cudaGetSymbolAddress((void**)&zx, g_zx);

    prep_wh<<<(9*256*64 + 255) / 256, 256>>>(Wh);
    prep_wx<<<(256*80 + 255) / 256, 256>>>(Wx, bias);
    zero_state<<<(NPIX/8 + 255) / 256, 256>>>();
    xconv_mma<<<dim3(12, 6, 128), 512, SMEM_PRE>>>(x, zx);

    for (int t = 0; t < TT; t++) {
        const __nv_bfloat16* hhi = (t & 1) ? hh1 : hh0;
        const __nv_bfloat16* hli = (t & 1) ? hl1 : hl0;
        __nv_bfloat16* hho = (t & 1) ? hh0 : hh1;
        __nv_bfloat16* hlo = (t & 1) ? hl0 : hl1;
        step_mma<<<dim3(12, 6, BB), 512, SMEM_STEP>>>(hhi, hli, hho, hlo, c, zx,
                                                      out, t, (t == TT - 1) ? 1 : 0);
    }
}

// round 14
// speedup vs baseline: 2.2528x; 1.3129x over previous
#include <cuda_runtime.h>
#include <cuda_fp16.h>
#include <cstdint>

#define BB 8
#define TT 16
#define NPIX (8*96*96*64)
#define ZXN  301989888           // B*T*H*W * 256

// ---------------- persistent device state ----------------
__device__ __half g_hh0[NPIX], g_hh1[NPIX];   // h hi ping-pong (fp16)
__device__ __half g_hl0[NPIX], g_hl1[NPIX];   // h lo residual
__device__ float  g_c[NPIX];
__device__ float  g_zx[ZXN];                  // x-conv + bias, n-permuted, fp32
__device__ __half g_whp[9*256*64];            // [tap][n_new][k], fp16 hi
__device__ __half g_wxp[256*80];              // [n_new][k pad 80], fp16 hi
__device__ float  g_biasp[256];

// ---------------- helpers ----------------
__device__ __forceinline__ uint32_t smem_u32(const void* p) {
    uint32_t a;
    asm("{ .reg .u64 t; cvta.to.shared.u64 t, %1; cvt.u32.u64 %0, t; }" : "=r"(a) : "l"(p));
    return a;
}
__device__ __forceinline__ float hsig(float z) {
    return fminf(fmaxf(fmaf(z, 0.2f, 0.5f), 0.0f), 1.0f);
}

#define LDSM4(r0,r1,r2,r3,addr) \
    asm volatile("ldmatrix.sync.aligned.m8n8.x4.shared.b16 {%0,%1,%2,%3}, [%4];" \
                 : "=r"(r0),"=r"(r1),"=r"(r2),"=r"(r3) : "r"(addr))

#define MMA(d,a0,a1,a2,a3,b0,b1) \
    asm volatile("mma.sync.aligned.m16n8k16.row.col.f32.f16.f16.f32 " \
                 "{%0,%1,%2,%3},{%4,%5,%6,%7},{%8,%9},{%0,%1,%2,%3};" \
                 : "+f"((d)[0]),"+f"((d)[1]),"+f"((d)[2]),"+f"((d)[3]) \
                 : "r"(a0),"r"(a1),"r"(a2),"r"(a3),"r"(b0),"r"(b1))

#define CPA16(dst,src) \
    asm volatile("cp.async.cg.shared.global [%0], [%1], 16;" :: "r"(dst), "l"(src) : "memory")
#define CPA_COMMIT() asm volatile("cp.async.commit_group;" ::: "memory")
#define CPA_WAIT1()  asm volatile("cp.async.wait_group 1;" ::: "memory")
#define CPA_WAIT0()  asm volatile("cp.async.wait_group 0;" ::: "memory")

// ---------------- prep kernels ----------------
__global__ void prep_wh(const float* __restrict__ Wh) {
    int i = blockIdx.x * blockDim.x + threadIdx.x;
    if (i < 9*256*64) {
        int tap = i >> 14, rem = i & 16383, n = rem >> 6, k = rem & 63;
        int f = n >> 2, g = n & 3, no = g * 64 + f;
        g_whp[i] = __float2half_rn(Wh[(tap * 64 + k) * 256 + no]);
    }
}
__global__ void prep_wx(const float* __restrict__ Wx, const float* __restrict__ b) {
    int i = blockIdx.x * blockDim.x + threadIdx.x;
    if (i < 256*80) {
        int n = i / 80, k = i - n * 80;
        int f = n >> 2, g = n & 3, no = g * 64 + f;
        float v = (k < 72) ? Wx[k * 256 + no] : 0.f;
        g_wxp[i] = __float2half_rn(v);
        if (k == 0) g_biasp[n] = b[no];
    }
}
__global__ void zero_state() {
    int i = blockIdx.x * blockDim.x + threadIdx.x;
    if (i < NPIX/8) {
        float4 z4 = make_float4(0.f,0.f,0.f,0.f);
        ((float4*)g_c)[2*i]   = z4;
        ((float4*)g_c)[2*i+1] = z4;
        uint4 z = make_uint4(0,0,0,0);
        ((uint4*)g_hh0)[i] = z;
        ((uint4*)g_hl0)[i] = z;
    }
}

// ---------------- x-conv precompute ----------------
#define PXF 0
#define PXA_HI 5760
#define PXA_LO 28288
#define PB_HI 50816
#define SMEM_PRE 95872

__global__ __launch_bounds__(512,1)
void xconv_mma(const float* __restrict__ x, float* __restrict__ zx)
{
    extern __shared__ char smem[];
    const uint32_t sbb = smem_u32(smem);
    const int tid = threadIdx.x, lane = tid & 31, wid = tid >> 5;
    const int bx0 = blockIdx.x * 8, by0 = blockIdx.y * 16, bt = blockIdx.z;
    const int m0 = (wid >> 2) * 32, n0 = (wid & 3) * 64;

    // fp32 x halo: 18x10 px, 8 ch
    for (int i = tid; i < 1440; i += 512) {
        int pix = i >> 3, ch = i & 7;
        int r = pix / 10, c = pix - r * 10;
        int gy = by0 + r - 1, gx = bx0 + c - 1;
        float v = 0.f;
        if ((unsigned)gy < 96u && (unsigned)gx < 96u)
            v = x[((bt * 96 + gy) * 96 + gx) * 8 + ch];
        *(float*)(smem + PXF + (pix * 8 + ch) * 4) = v;
    }
    __syncthreads();

    // im2col A (128 px x 80 k), fp16 hi/lo, stride 176B
    for (int i = tid; i < 128 * 80; i += 512) {
        int p = i / 80, k = i - p * 80;
        float v = 0.f;
        if (k < 72) {
            int tap = k >> 3, ci = k & 7;
            int ky = tap / 3, kx = tap - ky * 3;
            int py = p >> 3, px = p & 7;
            v = *(float*)(smem + PXF + (((py + ky) * 10 + px + kx) * 8 + ci) * 4);
        }
        __half hi = __float2half_rn(v);
        *(__half*)(smem + PXA_HI + p * 176 + k * 2) = hi;
        *(__half*)(smem + PXA_LO + p * 176 + k * 2) =
            __float2half_rn(v - __half2float(hi));
    }
    // B hi: [256][80] -> stride 176B
    for (int i = tid; i < 2560; i += 512) {
        int row = i / 10, ch = i - row * 10;
        *(uint4*)(smem + PB_HI + row * 176 + ch * 16) =
            *(const uint4*)((const char*)g_wxp + row * 160 + ch * 16);
    }
    __syncthreads();

    const int grp = lane >> 3, lr = lane & 7;
    const int koff = (grp >> 1) * 8;
    const int am0 = m0 + lr + (grp & 1) * 8;
    const int am1 = am0 + 16;
    const uint32_t aP0 = sbb + PXA_HI + am0 * 176 + koff * 2;
    const uint32_t aP1 = sbb + PXA_HI + am1 * 176 + koff * 2;
    uint32_t bRel[4];
    #pragma unroll
    for (int ng = 0; ng < 4; ng++)
        bRel[ng] = (uint32_t)(n0 + ng * 16 + (grp & 1) * 8 + lr) * 176 + koff * 2;
    const uint32_t bB = sbb + PB_HI;

    float acc[2][8][4];
    #pragma unroll
    for (int mf = 0; mf < 2; mf++)
        #pragma unroll
        for (int nf = 0; nf < 8; nf++)
            #pragma unroll
            for (int q = 0; q < 4; q++) acc[mf][nf][q] = 0.f;

    #pragma unroll
    for (int ks = 0; ks < 5; ks++) {
        const uint32_t o = ks * 32;
        uint32_t ah[2][4], al[2][4], bm[4][4];
        LDSM4(ah[0][0],ah[0][1],ah[0][2],ah[0][3], aP0 + o);
        LDSM4(ah[1][0],ah[1][1],ah[1][2],ah[1][3], aP1 + o);
        LDSM4(al[0][0],al[0][1],al[0][2],al[0][3], aP0 + (PXA_LO-PXA_HI) + o);
        LDSM4(al[1][0],al[1][1],al[1][2],al[1][3], aP1 + (PXA_LO-PXA_HI) + o);
        #pragma unroll
        for (int ng = 0; ng < 4; ng++)
            LDSM4(bm[ng][0],bm[ng][1],bm[ng][2],bm[ng][3], bB + bRel[ng] + o);
        #pragma unroll
        for (int mf = 0; mf < 2; mf++)
            #pragma unroll
            for (int nf = 0; nf < 8; nf++) {
                int ng = nf >> 1, s = nf & 1;
                MMA(acc[mf][nf], ah[mf][0],ah[mf][1],ah[mf][2],ah[mf][3], bm[ng][s], bm[ng][s+2]);
                MMA(acc[mf][nf], al[mf][0],al[mf][1],al[mf][2],al[mf][3], bm[ng][s], bm[ng][s+2]);
            }
    }

    // store z_x (+bias), n_new-major
    #pragma unroll
    for (int mf = 0; mf < 2; mf++)
        #pragma unroll
        for (int nf = 0; nf < 8; nf++) {
            int coln = n0 + 8 * nf + 2 * (lane & 3);
            float b0 = __ldg(g_biasp + coln), b1 = __ldg(g_biasp + coln + 1);
            int ma = m0 + 16 * mf + (lane >> 2);
            int gya = by0 + (ma >> 3), gxa = bx0 + (ma & 7);
            int zA = ((bt * 96 + gya) * 96 + gxa) * 256 + coln;
            *(float2*)(zx + zA) = make_float2(acc[mf][nf][0] + b0, acc[mf][nf][1] + b1);
            int mb = ma + 8;
            int gyb = by0 + (mb >> 3), gxb = bx0 + (mb & 7);
            int zB = ((bt * 96 + gyb) * 96 + gxb) * 256 + coln;
            *(float2*)(zx + zB) = make_float2(acc[mf][nf][2] + b0, acc[mf][nf][3] + b1);
        }
}

// ---------------- recurrent step ----------------
#define SHH 0
#define SHL 25920
#define SBO 51840
#define SB_STAGE 36864
#define SMEM_STEP 125568

__device__ __forceinline__ void issueB(uint32_t sbb, int stage, int tap, int tid) {
    uint32_t dh = sbb + SBO + stage * SB_STAGE;
    const char* sh_ = (const char*)g_whp + tap * 32768;
    #pragma unroll
    for (int j = 0; j < 4; j++) {
        int i = tid + j * 512;
        int row = i >> 3, ch = i & 7;
        CPA16(dh + row * 144 + ch * 16, sh_ + row * 128 + ch * 16);
    }
    CPA_COMMIT();
}

__global__ __launch_bounds__(512,1)
void step_mma(const __half* __restrict__ hh_in, const __half* __restrict__ hl_in,
              __half* __restrict__ hh_out, __half* __restrict__ hl_out,
              float* __restrict__ c_st, const float* __restrict__ zx,
              float* __restrict__ out, int t, int wout)
{
    extern __shared__ char smem[];
    const uint32_t sbb = smem_u32(smem);
    const int tid = threadIdx.x, lane = tid & 31, wid = tid >> 5;
    const int bx0 = blockIdx.x * 8, by0 = blockIdx.y * 16, bb = blockIdx.z;
    const int m0 = (wid >> 2) * 32, n0 = (wid & 3) * 64;

    // h halo hi/lo: 18x10 px x 64 fp16, stride 144B
    for (int i = tid; i < 1440; i += 512) {
        int pix = i >> 3, ch = i & 7;
        int r = pix / 10, c = pix - r * 10;
        int gy = by0 + r - 1, gx = bx0 + c - 1;
        uint4 vh = make_uint4(0,0,0,0), vl = vh;
        if ((unsigned)gy < 96u && (unsigned)gx < 96u) {
            int b = ((bb * 96 + gy) * 96 + gx) * 64 + ch * 8;
            vh = *(const uint4*)(hh_in + b);
            vl = *(const uint4*)(hl_in + b);
        }
        *(uint4*)(smem + SHH + pix * 144 + ch * 16) = vh;
        *(uint4*)(smem + SHL + pix * 144 + ch * 16) = vl;
    }

    issueB(sbb, 0, 0, tid);
    issueB(sbb, 1, 1, tid);

    const int grp = lane >> 3, lr = lane & 7;
    const int koff = (grp >> 1) * 8;
    const int am0 = m0 + lr + (grp & 1) * 8;
    const int am1 = am0 + 16;
    const int pya0 = am0 >> 3, pxa0 = am0 & 7;
    const int pya1 = am1 >> 3, pxa1 = am1 & 7;
    uint32_t bRel[4];
    #pragma unroll
    for (int ng = 0; ng < 4; ng++)
        bRel[ng] = (uint32_t)(n0 + ng * 16 + (grp & 1) * 8 + lr) * 144 + koff * 2;

    float acc[2][8][4];
    #pragma unroll
    for (int mf = 0; mf < 2; mf++)
        #pragma unroll
        for (int nf = 0; nf < 8; nf++)
            #pragma unroll
            for (int q = 0; q < 4; q++) acc[mf][nf][q] = 0.f;

    __syncthreads();   // halo visible

    #pragma unroll 1
    for (int tap = 0; tap < 9; tap++) {
        if (tap < 7) { CPA_WAIT1(); } else { CPA_WAIT0(); }
        __syncthreads();
        const int ky = tap / 3, kx = tap - ky * 3;
        const uint32_t aH0 = sbb + SHH + (((pya0 + ky) * 10 + pxa0 + kx) * 144 + koff * 2);
        const uint32_t aH1 = sbb + SHH + (((pya1 + ky) * 10 + pxa1 + kx) * 144 + koff * 2);
        const uint32_t bB = sbb + SBO + (tap & 1) * SB_STAGE;

        #pragma unroll
        for (int ks = 0; ks < 4; ks++) {
            const uint32_t o = ks * 32;
            uint32_t ah[2][4], al[2][4], bm[4][4];
            LDSM4(ah[0][0],ah[0][1],ah[0][2],ah[0][3], aH0 + o);
            LDSM4(ah[1][0],ah[1][1],ah[1][2],ah[1][3], aH1 + o);
            LDSM4(al[0][0],al[0][1],al[0][2],al[0][3], aH0 + (SHL-SHH) + o);
            LDSM4(al[1][0],al[1][1],al[1][2],al[1][3], aH1 + (SHL-SHH) + o);
            #pragma unroll
            for (int ng = 0; ng < 4; ng++)
                LDSM4(bm[ng][0],bm[ng][1],bm[ng][2],bm[ng][3], bB + bRel[ng] + o);
            #pragma unroll
            for (int mf = 0; mf < 2; mf++)
                #pragma unroll
                for (int nf = 0; nf < 8; nf++) {
                    int ng = nf >> 1, s = nf & 1;
                    MMA(acc[mf][nf], ah[mf][0],ah[mf][1],ah[mf][2],ah[mf][3], bm[ng][s], bm[ng][s+2]);
                    MMA(acc[mf][nf], al[mf][0],al[mf][1],al[mf][2],al[mf][3], bm[ng][s], bm[ng][s+2]);
                }
        }
        __syncthreads();
        if (tap + 2 < 9) issueB(sbb, tap & 1, tap + 2, tid);
    }

    // ---- epilogue: butterfly gate exchange + LSTM update ----
    const int odd = lane & 1;
    #pragma unroll
    for (int mf = 0; mf < 2; mf++)
        #pragma unroll
        for (int nf = 0; nf < 8; nf++) {
            float c0 = acc[mf][nf][0], c1 = acc[mf][nf][1];
            float c2 = acc[mf][nf][2], c3 = acc[mf][nf][3];
            float e0 = __shfl_xor_sync(0xFFFFFFFFu, c0, 1);
            float e1 = __shfl_xor_sync(0xFFFFFFFFu, c1, 1);
            float e2 = __shfl_xor_sync(0xFFFFFFFFu, c2, 1);
            float e3 = __shfl_xor_sync(0xFFFFFFFFu, c3, 1);
            float zi = odd ? e2 : c0;
            float zf = odd ? e3 : c1;
            float zg = odd ? c2 : e0;
            float zo = odd ? c3 : e1;
            int m = m0 + 16 * mf + (lane >> 2) + (odd ? 8 : 0);
            int f = ((n0 + 8 * nf) >> 2) + ((lane & 3) >> 1);
            int gy = by0 + (m >> 3), gx = bx0 + (m & 7);
            int pixb = ((bb * 96 + gy) * 96 + gx) * 64 + f;
            int zxi = (((bb * 16 + t) * 96 + gy) * 96 + gx) * 256 + f * 4;
            float4 z4 = *(const float4*)(zx + zxi);
            zi += z4.x; zf += z4.y; zg += z4.z; zo += z4.w;
            float cin = c_st[pixb];
            float cn = hsig(zf) * cin + hsig(zi) * tanhf(zg);
            float hn = hsig(zo) * tanhf(cn);
            c_st[pixb] = cn;
            __half hhi = __float2half_rn(hn);
            hh_out[pixb] = hhi;
            hl_out[pixb] = __float2half_rn(hn - __half2float(hhi));
            if (wout) out[pixb] = hn;
        }
}

// ---------------- launcher ----------------
extern "C" void kernel_launch(void* const* d_in, const int* in_sizes, int n_in,
                              void* d_out, int out_size) {
    const float* x    = (const float*)d_in[0];
    const float* Wx   = (const float*)d_in[1];
    const float* Wh   = (const float*)d_in[2];
    const float* bias = (const float*)d_in[3];
    float* out = (float*)d_out;

    cudaFuncSetAttribute(xconv_mma, cudaFuncAttributeMaxDynamicSharedMemorySize, SMEM_PRE);
    cudaFuncSetAttribute(step_mma,  cudaFuncAttributeMaxDynamicSharedMemorySize, SMEM_STEP);

    __half *hh0, *hh1, *hl0, *hl1;
    float *c, *zx;
    cudaGetSymbolAddress((void**)&hh0, g_hh0);
    cudaGetSymbolAddress((void**)&hh1, g_hh1);
    cudaGetSymbolAddress((void**)&hl0, g_hl0);
    cudaGetSymbolAddress((void**)&hl1, g_hl1);
    cudaGetSymbolAddress((void**)&c,  g_c);
    cudaGetSymbolAddress((void**)&zx, g_zx);

    prep_wh<<<(9*256*64 + 255) / 256, 256>>>(Wh);
    prep_wx<<<(256*80 + 255) / 256, 256>>>(Wx, bias);
    zero_state<<<(NPIX/8 + 255) / 256, 256>>>();
    xconv_mma<<<dim3(12, 6, 128), 512, SMEM_PRE>>>(x, zx);

    for (int t = 0; t < TT; t++) {
        const __half* hhi = (t & 1) ? hh1 : hh0;
        const __half* hli = (t & 1) ? hl1 : hl0;
        __half* hho = (t & 1) ? hh0 : hh1;
        __half* hlo = (t & 1) ? hl0 : hl1;
        step_mma<<<dim3(12, 6, BB), 512, SMEM_STEP>>>(hhi, hli, hho, hlo, c, zx,
                                                      out, t, (t == TT - 1) ? 1 : 0);
    }
}